// round 7
// baseline (speedup 1.0000x reference)
#include <cuda_runtime.h>
#include <cuda_fp16.h>

#define N_NODES_C 50000
#define N_EDGES_C 800000
#define HID_C 64
#define N_GRAPHS_C 256
#define BN_EPS_C 1e-5f
#define GATE_EPS_C 1e-6f
#define SCAN_TILE 1024
#define N_TILES ((N_NODES_C + SCAN_TILE - 1) / SCAN_TILE)

// ---------------- persistent device scratch ----------------
// interleaved node features: per node, 32 float4 = (cur[2l], cur[2l+1], prev[2l], prev[2l+1])
__device__ float4 g_hfi[(size_t)N_NODES_C * 32];
__device__ __half2 g_efh[(size_t)N_EDGES_C * 32];  // edge features fp16 (dst-sorted)
__device__ float g_hpre[N_NODES_C * HID_C];        // pre-BN h_new
__device__ float g_norm[N_NODES_C];
__device__ int   g_deg[N_NODES_C];
__device__ int   g_cursor[N_NODES_C];
__device__ int   g_rowptr[N_NODES_C + 1];
__device__ int   g_srcs[N_EDGES_C];                // packed: src(16) | etype(2)<<16 | hidx(7)<<18
__device__ int   g_bsum[N_TILES];
__device__ int   g_boff[N_TILES];
__device__ float g_stats[4 * HID_C];               // [se, se2, sh, sh2]
__device__ float g_scale_h[HID_C], g_shift_h[HID_C];
__device__ float g_scale_e[HID_C], g_shift_e[HID_C];
__device__ float g_hg[N_GRAPHS_C * HID_C];
__device__ int   g_gcount[N_GRAPHS_C];

// ---- streaming (evict-first) access helpers for the big ef array ----
__device__ __forceinline__ unsigned long long mk_policy() {
    unsigned long long p;
    asm volatile("createpolicy.fractional.L2::evict_first.b64 %0, 1.0;" : "=l"(p));
    return p;
}
__device__ __forceinline__ unsigned ld_stream_b32(const void* ptr, unsigned long long pol) {
    unsigned v;
    asm volatile("ld.global.L2::cache_hint.b32 %0, [%1], %2;"
                 : "=r"(v) : "l"(ptr), "l"(pol));
    return v;
}
__device__ __forceinline__ void st_stream_b32(void* ptr, unsigned v, unsigned long long pol) {
    asm volatile("st.global.L2::cache_hint.b32 [%0], %1, %2;"
                 :: "l"(ptr), "r"(v), "l"(pol));
}

// sigmoid via single-MUFU hardware tanh: sigma(x) = 0.5*tanh(x/2) + 0.5
__device__ __forceinline__ float fast_sigmoid(float x) {
    float t;
    asm("tanh.approx.f32 %0, %1;" : "=f"(t) : "f"(x * 0.5f));
    return fmaf(t, 0.5f, 0.5f);
}

// ---------------- prep kernels ----------------

__global__ void k_init() {
    int i = blockIdx.x * blockDim.x + threadIdx.x;
    if (i < N_NODES_C) { g_deg[i] = 0; g_cursor[i] = 0; }
    if (i < N_GRAPHS_C * HID_C) g_hg[i] = 0.f;
    if (i < N_GRAPHS_C) g_gcount[i] = 0;
    if (i < 4 * HID_C) g_stats[i] = 0.f;
}

__global__ void k_deg(const int* __restrict__ dst, const int* __restrict__ graph_ids) {
    int i = blockIdx.x * blockDim.x + threadIdx.x;
    if (i < N_EDGES_C) atomicAdd(&g_deg[dst[i]], 1);
    if (i < N_NODES_C) atomicAdd(&g_gcount[graph_ids[i]], 1);
}

__global__ void k_nodeinit(const int* __restrict__ h, const float* __restrict__ node_emb) {
    int tid = threadIdx.x;
    int warp = tid >> 5, lane = tid & 31;
    int n = blockIdx.x * 8 + warp;
    if (n >= N_NODES_C) return;
    if (lane == 0) g_norm[n] = rsqrtf(fmaxf((float)g_deg[n], 1.f));
    int hi = h[n];
    float2 v = *(const float2*)(node_emb + hi * HID_C + 2 * lane);
    g_hfi[(size_t)n * 32 + lane] = make_float4(v.x, v.y, v.x, v.y);
}

// ---- 3-phase scan: deg -> rowptr ----
__global__ void k_scanA() {
    __shared__ int s[32];
    int b = blockIdx.x, tid = threadIdx.x;
    int i = b * SCAN_TILE + tid;
    int v = (i < N_NODES_C) ? g_deg[i] : 0;
    #pragma unroll
    for (int off = 16; off > 0; off >>= 1) v += __shfl_down_sync(0xFFFFFFFFu, v, off);
    if ((tid & 31) == 0) s[tid >> 5] = v;
    __syncthreads();
    if (tid < 32) {
        int w = s[tid];
        #pragma unroll
        for (int off = 16; off > 0; off >>= 1) w += __shfl_down_sync(0xFFFFFFFFu, w, off);
        if (tid == 0) g_bsum[b] = w;
    }
}

__global__ void k_scanB() {
    int tid = threadIdx.x;
    int v = (tid < N_TILES) ? g_bsum[tid] : 0;
    int x = v;
    #pragma unroll
    for (int off = 1; off < 64; off <<= 1) {
        int t = __shfl_up_sync(0xFFFFFFFFu, x, off);
        if ((tid & 31) >= off) x += t;
    }
    __shared__ int s_half;
    if (tid == 31) s_half = x;
    __syncthreads();
    if (tid >= 32) x += s_half;
    if (tid < N_TILES) g_boff[tid] = x - v;
}

__global__ void k_scanC() {
    __shared__ int s_warp[32];
    int b = blockIdx.x, tid = threadIdx.x;
    int lane = tid & 31, warp = tid >> 5;
    int i = b * SCAN_TILE + tid;
    int v = (i < N_NODES_C) ? g_deg[i] : 0;
    int x = v;
    #pragma unroll
    for (int off = 1; off < 32; off <<= 1) {
        int t = __shfl_up_sync(0xFFFFFFFFu, x, off);
        if (lane >= off) x += t;
    }
    if (lane == 31) s_warp[warp] = x;
    __syncthreads();
    if (warp == 0) {
        int w = s_warp[lane];
        #pragma unroll
        for (int off = 1; off < 32; off <<= 1) {
            int t = __shfl_up_sync(0xFFFFFFFFu, w, off);
            if (lane >= off) w += t;
        }
        s_warp[lane] = w;
    }
    __syncthreads();
    int incl = x + (warp > 0 ? s_warp[warp - 1] : 0) + g_boff[b];
    if (i < N_NODES_C) g_rowptr[i + 1] = incl;
    if (b == 0 && tid == 0) g_rowptr[0] = 0;
}

// counting-sort permute; packs src | etype<<16 | h[src]<<18
__global__ void k_permute(const int* __restrict__ e, const int* __restrict__ src,
                          const int* __restrict__ dst, const int* __restrict__ h) {
    int i = blockIdx.x * blockDim.x + threadIdx.x;
    if (i >= N_EDGES_C) return;
    int d = dst[i];
    int s = src[i];
    int pos = g_rowptr[d] + atomicAdd(&g_cursor[d], 1);
    g_srcs[pos] = s | (e[i] << 16) | (h[s] << 18);
}

// ---------------- fused layer pass ----------------
// 2 warps per node (contiguous half-ranges of the edge list), smem combine.
// L0: neighbor features from L1-resident node_emb table (no hfi gather).
// L1: prev from node_emb table, cur as 8B float2 gather.
// L2/3: full float4 gather.
template<int L>
__global__ void __launch_bounds__(256) k_fused(const float* __restrict__ edge_emb,
                                               const float* __restrict__ node_emb) {
    __shared__ float s_emb[4 * HID_C];   // L<=1: edge-type embeddings
    __shared__ float s_acc[256];
    __shared__ float4 s_part[8][32];     // per-warp partial (mx,my,dx,dy)
    int tid = threadIdx.x;
    if (L <= 1) s_emb[tid] = edge_emb[tid];
    s_acc[tid] = 0.f;
    __syncthreads();
    int warp = tid >> 5, lane = tid & 31;
    int half = warp & 1;
    int n = blockIdx.x * 4 + (warp >> 1);   // grid is exactly N/4 blocks

    unsigned long long pol = mk_policy();
    float4 f4 = g_hfi[(size_t)n * 32 + lane];
    float hdcx = f4.x, hdcy = f4.y, hdpx = f4.z, hdpy = f4.w;
    float sce_x = 0.f, sce_y = 0.f, she_x = 0.f, she_y = 0.f;
    if (L >= 1) {
        sce_x = g_scale_e[2 * lane]; sce_y = g_scale_e[2 * lane + 1];
        she_x = g_shift_e[2 * lane]; she_y = g_shift_e[2 * lane + 1];
    }
    float mx = 0.f, my = 0.f, dx = 0.f, dy = 0.f;
    float sex = 0.f, sey = 0.f, se2x = 0.f, se2y = 0.f;
    int beg = g_rowptr[n], end = g_rowptr[n + 1];
    int cnt = end - beg;
    int c0 = (cnt + 1) >> 1;
    int myBeg = beg + half * c0;
    int myEnd = half ? end : beg + c0;

    // fetch neighbor features for one edge
    auto fetch_nf = [&](int sp, float2& nc, float2& np) {
        int s = sp & 0xFFFF;
        if (L == 0) {
            int hidx = (sp >> 18) & 0x7F;
            nc = __ldg((const float2*)(node_emb + hidx * HID_C + 2 * lane));
            np = make_float2(0.f, 0.f);
        } else if (L == 1) {
            nc = *(const float2*)&g_hfi[(size_t)s * 32 + lane];   // cur half (8B)
            int hidx = (sp >> 18) & 0x7F;
            np = __ldg((const float2*)(node_emb + hidx * HID_C + 2 * lane));
        } else {
            float4 v = g_hfi[(size_t)s * 32 + lane];
            nc = make_float2(v.x, v.y);
            np = make_float2(v.z, v.w);
        }
    };

    auto compute = [&](int k, float2 nc, float2 np, float ns, float rawx, float rawy) {
        float efx, efy;
        if (L == 0) {
            efx = rawx; efy = rawy;
        } else {
            float epx = np.x + hdpx + rawx;
            float epy = np.y + hdpy + rawy;
            efx = rawx + fmaxf(epx * sce_x + she_x, 0.f);
            efy = rawy + fmaxf(epy * sce_y + she_y, 0.f);
            if (L < 3) {
                __half2 hv = __floats2half2_rn(efx, efy);
                st_stream_b32(&g_efh[(size_t)k * 32 + lane], *(unsigned*)&hv, pol);
            }
        }
        float ex = nc.x + hdcx + efx;
        float ey = nc.y + hdcy + efy;
        float sgx = fast_sigmoid(ex);
        float sgy = fast_sigmoid(ey);
        mx += sgx * nc.x * ns; my += sgy * nc.y * ns;
        dx += sgx; dy += sgy;
        if (L < 3) { sex += ex; sey += ey; se2x += ex * ex; se2y += ey * ey; }
    };

    int k = myBeg;
    for (; k + 3 < myEnd; k += 4) {
        int sp[4];
        #pragma unroll
        for (int j = 0; j < 4; j++) sp[j] = g_srcs[k + j];
        float2 nc[4], np[4];
        #pragma unroll
        for (int j = 0; j < 4; j++) fetch_nf(sp[j], nc[j], np[j]);
        float ns[4];
        #pragma unroll
        for (int j = 0; j < 4; j++) ns[j] = g_norm[sp[j] & 0xFFFF];
        float rawx[4], rawy[4];
        #pragma unroll
        for (int j = 0; j < 4; j++) {
            if (L <= 1) {
                int et = (sp[j] >> 16) & 3;
                rawx[j] = s_emb[et * HID_C + 2 * lane];
                rawy[j] = s_emb[et * HID_C + 2 * lane + 1];
            } else {
                unsigned u = ld_stream_b32(&g_efh[(size_t)(k + j) * 32 + lane], pol);
                float2 r = __half22float2(*(__half2*)&u);
                rawx[j] = r.x; rawy[j] = r.y;
            }
        }
        #pragma unroll
        for (int j = 0; j < 4; j++) compute(k + j, nc[j], np[j], ns[j], rawx[j], rawy[j]);
    }
    for (; k < myEnd; k++) {
        int sp = g_srcs[k];
        float2 nc, np;
        fetch_nf(sp, nc, np);
        float ns = g_norm[sp & 0xFFFF];
        float rawx, rawy;
        if (L <= 1) {
            int et = (sp >> 16) & 3;
            rawx = s_emb[et * HID_C + 2 * lane];
            rawy = s_emb[et * HID_C + 2 * lane + 1];
        } else {
            unsigned u = ld_stream_b32(&g_efh[(size_t)k * 32 + lane], pol);
            float2 r = __half22float2(*(__half2*)&u);
            rawx = r.x; rawy = r.y;
        }
        compute(k, nc, np, ns, rawx, rawy);
    }

    // e-stats: global sums, both halves contribute directly
    if (L < 3) {
        atomicAdd(&s_acc[2 * lane], sex);
        atomicAdd(&s_acc[2 * lane + 1], sey);
        atomicAdd(&s_acc[64 + 2 * lane], se2x);
        atomicAdd(&s_acc[64 + 2 * lane + 1], se2y);
    }
    s_part[warp][lane] = make_float4(mx, my, dx, dy);
    __syncthreads();

    if (half == 0) {
        float4 o = s_part[warp + 1][lane];
        mx += o.x; my += o.y; dx += o.z; dy += o.w;
        float nn = g_norm[n];
        float hpx = (hdcx * nn + mx / (dx + GATE_EPS_C)) * nn;
        float hpy = (hdcy * nn + my / (dy + GATE_EPS_C)) * nn;
        *(float2*)(&g_hpre[n * HID_C + 2 * lane]) = make_float2(hpx, hpy);
        atomicAdd(&s_acc[128 + 2 * lane], hpx);
        atomicAdd(&s_acc[128 + 2 * lane + 1], hpy);
        atomicAdd(&s_acc[192 + 2 * lane], hpx * hpx);
        atomicAdd(&s_acc[192 + 2 * lane + 1], hpy * hpy);
    }
    __syncthreads();
    atomicAdd(&g_stats[tid], s_acc[tid]);
}

// BN scale/shift for layer l; reset stats
__global__ void k_finalize(const float* __restrict__ bhg, const float* __restrict__ bhb,
                           const float* __restrict__ beg_, const float* __restrict__ beb, int l) {
    int f = threadIdx.x;
    float se = g_stats[f], se2 = g_stats[64 + f];
    float sh = g_stats[128 + f], sh2 = g_stats[192 + f];
    float mue = se / (float)N_EDGES_C;
    float vare = se2 / (float)N_EDGES_C - mue * mue;
    float sce = beg_[l * HID_C + f] * rsqrtf(vare + BN_EPS_C);
    g_scale_e[f] = sce;
    g_shift_e[f] = beb[l * HID_C + f] - mue * sce;
    float muh = sh / (float)N_NODES_C;
    float varh = sh2 / (float)N_NODES_C - muh * muh;
    float sch = bhg[l * HID_C + f] * rsqrtf(varh + BN_EPS_C);
    g_scale_h[f] = sch;
    g_shift_h[f] = bhb[l * HID_C + f] - muh * sch;
    g_stats[f] = 0.f; g_stats[64 + f] = 0.f; g_stats[128 + f] = 0.f; g_stats[192 + f] = 0.f;
}

// node update on interleaved array: (cur, prev) -> (cur + relu(BN(hpre)), cur)
__global__ void k_Bh() {
    int i = blockIdx.x * blockDim.x + threadIdx.x;
    if (i >= N_NODES_C * 32) return;
    int lane = i & 31;
    float4 f4 = g_hfi[i];
    float2 hp = *(const float2*)(&g_hpre[i * 2]);
    float vx = fmaxf(hp.x * g_scale_h[2 * lane] + g_shift_h[2 * lane], 0.f);
    float vy = fmaxf(hp.y * g_scale_h[2 * lane + 1] + g_shift_h[2 * lane + 1], 0.f);
    g_hfi[i] = make_float4(f4.x + vx, f4.y + vy, f4.x, f4.y);
}

// final node update fused with per-graph sum pooling
__global__ void k_BhPool(const int* __restrict__ graph_ids) {
    int i = blockIdx.x * blockDim.x + threadIdx.x;
    if (i >= N_NODES_C * 32) return;
    int lane = i & 31;
    int n = i >> 5;
    float4 f4 = g_hfi[i];
    float2 hp = *(const float2*)(&g_hpre[i * 2]);
    float vx = f4.x + fmaxf(hp.x * g_scale_h[2 * lane] + g_shift_h[2 * lane], 0.f);
    float vy = f4.y + fmaxf(hp.y * g_scale_h[2 * lane + 1] + g_shift_h[2 * lane + 1], 0.f);
    int g = graph_ids[n];
    atomicAdd(&g_hg[(g << 6) + 2 * lane], vx);
    atomicAdd(&g_hg[(g << 6) + 2 * lane + 1], vy);
}

// final 3-layer MLP, one thread per graph
__global__ void k_mlp(const float* __restrict__ W1, const float* __restrict__ b1,
                      const float* __restrict__ W2, const float* __restrict__ b2,
                      const float* __restrict__ W3, const float* __restrict__ b3,
                      float* __restrict__ out) {
    __shared__ float sW1[64 * 32], sW2[32 * 16], sb1[32], sb2[16], sW3[16], sb3;
    int tid = threadIdx.x;
    for (int i = tid; i < 64 * 32; i += 256) sW1[i] = W1[i];
    for (int i = tid; i < 32 * 16; i += 256) sW2[i] = W2[i];
    if (tid < 32) sb1[tid] = b1[tid];
    if (tid < 16) { sb2[tid] = b2[tid]; sW3[tid] = W3[tid]; }
    if (tid == 0) sb3 = b3[0];
    __syncthreads();
    int g = tid;
    float inv = 1.f / fmaxf((float)g_gcount[g], 1.f);
    float x[64];
    #pragma unroll
    for (int k = 0; k < 64; k++) x[k] = g_hg[g * 64 + k] * inv;
    float y[32];
    #pragma unroll
    for (int j = 0; j < 32; j++) {
        float a = sb1[j];
        #pragma unroll
        for (int k = 0; k < 64; k++) a += x[k] * sW1[k * 32 + j];
        y[j] = fmaxf(a, 0.f);
    }
    float z[16];
    #pragma unroll
    for (int j = 0; j < 16; j++) {
        float a = sb2[j];
        #pragma unroll
        for (int k = 0; k < 32; k++) a += y[k] * sW2[k * 16 + j];
        z[j] = fmaxf(a, 0.f);
    }
    float o = sb3;
    #pragma unroll
    for (int k = 0; k < 16; k++) o += z[k] * sW3[k];
    out[g] = o;
}

// ---------------- launch ----------------
extern "C" void kernel_launch(void* const* d_in, const int* in_sizes, int n_in,
                              void* d_out, int out_size) {
    const int*   h         = (const int*)d_in[0];
    const int*   e         = (const int*)d_in[1];
    const int*   src       = (const int*)d_in[2];
    const int*   dst       = (const int*)d_in[3];
    const int*   graph_ids = (const int*)d_in[4];
    const float* node_emb  = (const float*)d_in[5];
    const float* edge_emb  = (const float*)d_in[6];
    const float* bn_h_g    = (const float*)d_in[7];
    const float* bn_h_b    = (const float*)d_in[8];
    const float* bn_e_g    = (const float*)d_in[9];
    const float* bn_e_b    = (const float*)d_in[10];
    const float* W1        = (const float*)d_in[11];
    const float* b1        = (const float*)d_in[12];
    const float* W2        = (const float*)d_in[13];
    const float* b2        = (const float*)d_in[14];
    const float* W3        = (const float*)d_in[15];
    const float* b3        = (const float*)d_in[16];
    float* out = (float*)d_out;

    const int NODE_WARP_BLOCKS = (N_NODES_C + 7) / 8;
    const int FUSED_BLOCKS = N_NODES_C / 4;          // 12500, exact
    const int NL_BLOCKS = (N_NODES_C * 32 + 255) / 256;

    k_init<<<(N_NODES_C + 255) / 256, 256>>>();
    k_deg<<<(N_EDGES_C + 255) / 256, 256>>>(dst, graph_ids);
    k_nodeinit<<<NODE_WARP_BLOCKS, 256>>>(h, node_emb);
    k_scanA<<<N_TILES, SCAN_TILE>>>();
    k_scanB<<<1, 64>>>();
    k_scanC<<<N_TILES, SCAN_TILE>>>();
    k_permute<<<(N_EDGES_C + 255) / 256, 256>>>(e, src, dst, h);

    k_fused<0><<<FUSED_BLOCKS, 256>>>(edge_emb, node_emb);
    k_finalize<<<1, 64>>>(bn_h_g, bn_h_b, bn_e_g, bn_e_b, 0);
    k_Bh<<<NL_BLOCKS, 256>>>();
    k_fused<1><<<FUSED_BLOCKS, 256>>>(edge_emb, node_emb);
    k_finalize<<<1, 64>>>(bn_h_g, bn_h_b, bn_e_g, bn_e_b, 1);
    k_Bh<<<NL_BLOCKS, 256>>>();
    k_fused<2><<<FUSED_BLOCKS, 256>>>(edge_emb, node_emb);
    k_finalize<<<1, 64>>>(bn_h_g, bn_h_b, bn_e_g, bn_e_b, 2);
    k_Bh<<<NL_BLOCKS, 256>>>();
    k_fused<3><<<FUSED_BLOCKS, 256>>>(edge_emb, node_emb);
    k_finalize<<<1, 64>>>(bn_h_g, bn_h_b, bn_e_g, bn_e_b, 3);
    k_BhPool<<<NL_BLOCKS, 256>>>(graph_ids);

    k_mlp<<<1, 256>>>(W1, b1, W2, b2, W3, b3, out);
    (void)in_sizes; (void)n_in; (void)out_size;
}

// round 8
// speedup vs baseline: 1.0788x; 1.0788x over previous
#include <cuda_runtime.h>
#include <cuda_fp16.h>

#define N_NODES_C 50000
#define N_EDGES_C 800000
#define HID_C 64
#define N_GRAPHS_C 256
#define BN_EPS_C 1e-5f
#define GATE_EPS_C 1e-6f
#define SCAN_TILE 1024
#define N_TILES ((N_NODES_C + SCAN_TILE - 1) / SCAN_TILE)

// ---------------- persistent device scratch ----------------
// interleaved node features: per node, 32 float4 = (cur[2l], cur[2l+1], prev[2l], prev[2l+1])
__device__ float4 g_hfi[(size_t)N_NODES_C * 32];
__device__ __half2 g_efh[(size_t)N_EDGES_C * 32];  // edge features fp16 (dst-sorted)
__device__ float g_hpre[N_NODES_C * HID_C];        // pre-BN h_new
__device__ float g_norm[N_NODES_C];
__device__ int   g_deg[N_NODES_C];
__device__ int   g_cursor[N_NODES_C];
__device__ int   g_rowptr[N_NODES_C + 1];
__device__ int   g_srcs[N_EDGES_C];                // packed: src(16) | etype(2)<<16 | hidx(7)<<18
__device__ int   g_bsum[N_TILES];
__device__ int   g_boff[N_TILES];
__device__ float g_stats[4 * HID_C];               // [se, se2, sh, sh2]
__device__ float g_scale_h[HID_C], g_shift_h[HID_C];
__device__ float g_scale_e[HID_C], g_shift_e[HID_C];
__device__ float g_hg[N_GRAPHS_C * HID_C];
__device__ int   g_gcount[N_GRAPHS_C];

// ---- streaming (evict-first) access helpers for the big ef array ----
__device__ __forceinline__ unsigned long long mk_policy() {
    unsigned long long p;
    asm volatile("createpolicy.fractional.L2::evict_first.b64 %0, 1.0;" : "=l"(p));
    return p;
}
__device__ __forceinline__ unsigned ld_stream_b32(const void* ptr, unsigned long long pol) {
    unsigned v;
    asm volatile("ld.global.L2::cache_hint.b32 %0, [%1], %2;"
                 : "=r"(v) : "l"(ptr), "l"(pol));
    return v;
}
__device__ __forceinline__ void st_stream_b32(void* ptr, unsigned v, unsigned long long pol) {
    asm volatile("st.global.L2::cache_hint.b32 [%0], %1, %2;"
                 :: "l"(ptr), "r"(v), "l"(pol));
}

// sigmoid via single-MUFU hardware tanh: sigma(x) = 0.5*tanh(x/2) + 0.5
__device__ __forceinline__ float fast_sigmoid(float x) {
    float t;
    asm("tanh.approx.f32 %0, %1;" : "=f"(t) : "f"(x * 0.5f));
    return fmaf(t, 0.5f, 0.5f);
}

// ---------------- prep kernels ----------------

__global__ void k_init() {
    int i = blockIdx.x * blockDim.x + threadIdx.x;
    if (i < N_NODES_C) { g_deg[i] = 0; g_cursor[i] = 0; }
    if (i < N_GRAPHS_C * HID_C) g_hg[i] = 0.f;
    if (i < N_GRAPHS_C) g_gcount[i] = 0;
    if (i < 4 * HID_C) g_stats[i] = 0.f;
}

__global__ void k_deg(const int* __restrict__ dst, const int* __restrict__ graph_ids) {
    int i = blockIdx.x * blockDim.x + threadIdx.x;
    if (i < N_EDGES_C) atomicAdd(&g_deg[dst[i]], 1);
    if (i < N_NODES_C) atomicAdd(&g_gcount[graph_ids[i]], 1);
}

__global__ void k_nodeinit(const int* __restrict__ h, const float* __restrict__ node_emb) {
    int tid = threadIdx.x;
    int warp = tid >> 5, lane = tid & 31;
    int n = blockIdx.x * 8 + warp;
    if (n >= N_NODES_C) return;
    if (lane == 0) g_norm[n] = rsqrtf(fmaxf((float)g_deg[n], 1.f));
    int hi = h[n];
    float2 v = *(const float2*)(node_emb + hi * HID_C + 2 * lane);
    g_hfi[(size_t)n * 32 + lane] = make_float4(v.x, v.y, v.x, v.y);
}

// ---- 3-phase scan: deg -> rowptr ----
__global__ void k_scanA() {
    __shared__ int s[32];
    int b = blockIdx.x, tid = threadIdx.x;
    int i = b * SCAN_TILE + tid;
    int v = (i < N_NODES_C) ? g_deg[i] : 0;
    #pragma unroll
    for (int off = 16; off > 0; off >>= 1) v += __shfl_down_sync(0xFFFFFFFFu, v, off);
    if ((tid & 31) == 0) s[tid >> 5] = v;
    __syncthreads();
    if (tid < 32) {
        int w = s[tid];
        #pragma unroll
        for (int off = 16; off > 0; off >>= 1) w += __shfl_down_sync(0xFFFFFFFFu, w, off);
        if (tid == 0) g_bsum[b] = w;
    }
}

__global__ void k_scanB() {
    int tid = threadIdx.x;
    int v = (tid < N_TILES) ? g_bsum[tid] : 0;
    int x = v;
    #pragma unroll
    for (int off = 1; off < 64; off <<= 1) {
        int t = __shfl_up_sync(0xFFFFFFFFu, x, off);
        if ((tid & 31) >= off) x += t;
    }
    __shared__ int s_half;
    if (tid == 31) s_half = x;
    __syncthreads();
    if (tid >= 32) x += s_half;
    if (tid < N_TILES) g_boff[tid] = x - v;
}

__global__ void k_scanC() {
    __shared__ int s_warp[32];
    int b = blockIdx.x, tid = threadIdx.x;
    int lane = tid & 31, warp = tid >> 5;
    int i = b * SCAN_TILE + tid;
    int v = (i < N_NODES_C) ? g_deg[i] : 0;
    int x = v;
    #pragma unroll
    for (int off = 1; off < 32; off <<= 1) {
        int t = __shfl_up_sync(0xFFFFFFFFu, x, off);
        if (lane >= off) x += t;
    }
    if (lane == 31) s_warp[warp] = x;
    __syncthreads();
    if (warp == 0) {
        int w = s_warp[lane];
        #pragma unroll
        for (int off = 1; off < 32; off <<= 1) {
            int t = __shfl_up_sync(0xFFFFFFFFu, w, off);
            if (lane >= off) w += t;
        }
        s_warp[lane] = w;
    }
    __syncthreads();
    int incl = x + (warp > 0 ? s_warp[warp - 1] : 0) + g_boff[b];
    if (i < N_NODES_C) g_rowptr[i + 1] = incl;
    if (b == 0 && tid == 0) g_rowptr[0] = 0;
}

// counting-sort permute; packs src | etype<<16 | h[src]<<18
__global__ void k_permute(const int* __restrict__ e, const int* __restrict__ src,
                          const int* __restrict__ dst, const int* __restrict__ h) {
    int i = blockIdx.x * blockDim.x + threadIdx.x;
    if (i >= N_EDGES_C) return;
    int d = dst[i];
    int s = src[i];
    int pos = g_rowptr[d] + atomicAdd(&g_cursor[d], 1);
    g_srcs[pos] = s | (e[i] << 16) | (h[s] << 18);
}

// ---------------- fused layer pass (1 warp/node, 4-wide, node_emb shortcuts) ----------------
// L0: neighbor cur from L1-resident node_emb (no hfi gather at all).
// L1: cur as 8B float2 gather; prev from node_emb.
// L2/3: full float4 gather.
template<int L>
__global__ void __launch_bounds__(256) k_fused(const float* __restrict__ edge_emb,
                                               const float* __restrict__ node_emb) {
    __shared__ float s_emb[4 * HID_C];
    __shared__ float s_acc[256];
    int tid = threadIdx.x;
    if (L <= 1) s_emb[tid] = edge_emb[tid];
    s_acc[tid] = 0.f;
    __syncthreads();
    int warp = tid >> 5, lane = tid & 31;
    int n = blockIdx.x * 8 + warp;
    if (n < N_NODES_C) {
        unsigned long long pol = mk_policy();
        float4 f4 = g_hfi[(size_t)n * 32 + lane];
        float hdcx = f4.x, hdcy = f4.y, hdpx = f4.z, hdpy = f4.w;
        float sce_x = 0.f, sce_y = 0.f, she_x = 0.f, she_y = 0.f;
        if (L >= 1) {
            sce_x = g_scale_e[2 * lane]; sce_y = g_scale_e[2 * lane + 1];
            she_x = g_shift_e[2 * lane]; she_y = g_shift_e[2 * lane + 1];
        }
        float nn = g_norm[n];
        float mx = 0.f, my = 0.f, dx = 0.f, dy = 0.f;
        float sex = 0.f, sey = 0.f, se2x = 0.f, se2y = 0.f;
        int beg = g_rowptr[n], end = g_rowptr[n + 1];

        auto fetch_nf = [&](int sp, float2& nc, float2& np) {
            int s = sp & 0xFFFF;
            if (L == 0) {
                int hidx = (sp >> 18) & 0x7F;
                nc = __ldg((const float2*)(node_emb + hidx * HID_C + 2 * lane));
                np = make_float2(0.f, 0.f);
            } else if (L == 1) {
                nc = *(const float2*)&g_hfi[(size_t)s * 32 + lane];   // cur half (8B)
                int hidx = (sp >> 18) & 0x7F;
                np = __ldg((const float2*)(node_emb + hidx * HID_C + 2 * lane));
            } else {
                float4 v = g_hfi[(size_t)s * 32 + lane];
                nc = make_float2(v.x, v.y);
                np = make_float2(v.z, v.w);
            }
        };

        auto compute = [&](int k, float2 nc, float2 np, float ns, float rawx, float rawy) {
            float efx, efy;
            if (L == 0) {
                efx = rawx; efy = rawy;
            } else {
                float epx = np.x + hdpx + rawx;
                float epy = np.y + hdpy + rawy;
                efx = rawx + fmaxf(epx * sce_x + she_x, 0.f);
                efy = rawy + fmaxf(epy * sce_y + she_y, 0.f);
                if (L < 3) {
                    __half2 hv = __floats2half2_rn(efx, efy);
                    st_stream_b32(&g_efh[(size_t)k * 32 + lane], *(unsigned*)&hv, pol);
                }
            }
            float ex = nc.x + hdcx + efx;
            float ey = nc.y + hdcy + efy;
            float sgx = fast_sigmoid(ex);
            float sgy = fast_sigmoid(ey);
            mx += sgx * nc.x * ns; my += sgy * nc.y * ns;
            dx += sgx; dy += sgy;
            if (L < 3) { sex += ex; sey += ey; se2x += ex * ex; se2y += ey * ey; }
        };

        int k = beg;
        for (; k + 3 < end; k += 4) {
            int sp[4];
            #pragma unroll
            for (int j = 0; j < 4; j++) sp[j] = g_srcs[k + j];
            float2 nc[4], np[4];
            #pragma unroll
            for (int j = 0; j < 4; j++) fetch_nf(sp[j], nc[j], np[j]);
            float ns[4];
            #pragma unroll
            for (int j = 0; j < 4; j++) ns[j] = g_norm[sp[j] & 0xFFFF];
            float rawx[4], rawy[4];
            #pragma unroll
            for (int j = 0; j < 4; j++) {
                if (L <= 1) {
                    int et = (sp[j] >> 16) & 3;
                    rawx[j] = s_emb[et * HID_C + 2 * lane];
                    rawy[j] = s_emb[et * HID_C + 2 * lane + 1];
                } else {
                    unsigned u = ld_stream_b32(&g_efh[(size_t)(k + j) * 32 + lane], pol);
                    float2 r = __half22float2(*(__half2*)&u);
                    rawx[j] = r.x; rawy[j] = r.y;
                }
            }
            #pragma unroll
            for (int j = 0; j < 4; j++) compute(k + j, nc[j], np[j], ns[j], rawx[j], rawy[j]);
        }
        for (; k < end; k++) {
            int sp = g_srcs[k];
            float2 nc, np;
            fetch_nf(sp, nc, np);
            float ns = g_norm[sp & 0xFFFF];
            float rawx, rawy;
            if (L <= 1) {
                int et = (sp >> 16) & 3;
                rawx = s_emb[et * HID_C + 2 * lane];
                rawy = s_emb[et * HID_C + 2 * lane + 1];
            } else {
                unsigned u = ld_stream_b32(&g_efh[(size_t)k * 32 + lane], pol);
                float2 r = __half22float2(*(__half2*)&u);
                rawx = r.x; rawy = r.y;
            }
            compute(k, nc, np, ns, rawx, rawy);
        }

        float hpx = (hdcx * nn + mx / (dx + GATE_EPS_C)) * nn;
        float hpy = (hdcy * nn + my / (dy + GATE_EPS_C)) * nn;
        *(float2*)(&g_hpre[n * HID_C + 2 * lane]) = make_float2(hpx, hpy);
        if (L < 3) {
            atomicAdd(&s_acc[2 * lane], sex);
            atomicAdd(&s_acc[2 * lane + 1], sey);
            atomicAdd(&s_acc[64 + 2 * lane], se2x);
            atomicAdd(&s_acc[64 + 2 * lane + 1], se2y);
        }
        atomicAdd(&s_acc[128 + 2 * lane], hpx);
        atomicAdd(&s_acc[128 + 2 * lane + 1], hpy);
        atomicAdd(&s_acc[192 + 2 * lane], hpx * hpx);
        atomicAdd(&s_acc[192 + 2 * lane + 1], hpy * hpy);
    }
    __syncthreads();
    atomicAdd(&g_stats[tid], s_acc[tid]);
}

// BN scale/shift for layer l; reset stats
__global__ void k_finalize(const float* __restrict__ bhg, const float* __restrict__ bhb,
                           const float* __restrict__ beg_, const float* __restrict__ beb, int l) {
    int f = threadIdx.x;
    float se = g_stats[f], se2 = g_stats[64 + f];
    float sh = g_stats[128 + f], sh2 = g_stats[192 + f];
    float mue = se / (float)N_EDGES_C;
    float vare = se2 / (float)N_EDGES_C - mue * mue;
    float sce = beg_[l * HID_C + f] * rsqrtf(vare + BN_EPS_C);
    g_scale_e[f] = sce;
    g_shift_e[f] = beb[l * HID_C + f] - mue * sce;
    float muh = sh / (float)N_NODES_C;
    float varh = sh2 / (float)N_NODES_C - muh * muh;
    float sch = bhg[l * HID_C + f] * rsqrtf(varh + BN_EPS_C);
    g_scale_h[f] = sch;
    g_shift_h[f] = bhb[l * HID_C + f] - muh * sch;
    g_stats[f] = 0.f; g_stats[64 + f] = 0.f; g_stats[128 + f] = 0.f; g_stats[192 + f] = 0.f;
}

// node update on interleaved array: (cur, prev) -> (cur + relu(BN(hpre)), cur)
__global__ void k_Bh() {
    int i = blockIdx.x * blockDim.x + threadIdx.x;
    if (i >= N_NODES_C * 32) return;
    int lane = i & 31;
    float4 f4 = g_hfi[i];
    float2 hp = *(const float2*)(&g_hpre[i * 2]);
    float vx = fmaxf(hp.x * g_scale_h[2 * lane] + g_shift_h[2 * lane], 0.f);
    float vy = fmaxf(hp.y * g_scale_h[2 * lane + 1] + g_shift_h[2 * lane + 1], 0.f);
    g_hfi[i] = make_float4(f4.x + vx, f4.y + vy, f4.x, f4.y);
}

// final node update fused with per-graph sum pooling
__global__ void k_BhPool(const int* __restrict__ graph_ids) {
    int i = blockIdx.x * blockDim.x + threadIdx.x;
    if (i >= N_NODES_C * 32) return;
    int lane = i & 31;
    int n = i >> 5;
    float4 f4 = g_hfi[i];
    float2 hp = *(const float2*)(&g_hpre[i * 2]);
    float vx = f4.x + fmaxf(hp.x * g_scale_h[2 * lane] + g_shift_h[2 * lane], 0.f);
    float vy = f4.y + fmaxf(hp.y * g_scale_h[2 * lane + 1] + g_shift_h[2 * lane + 1], 0.f);
    int g = graph_ids[n];
    atomicAdd(&g_hg[(g << 6) + 2 * lane], vx);
    atomicAdd(&g_hg[(g << 6) + 2 * lane + 1], vy);
}

// final 3-layer MLP, one thread per graph
__global__ void k_mlp(const float* __restrict__ W1, const float* __restrict__ b1,
                      const float* __restrict__ W2, const float* __restrict__ b2,
                      const float* __restrict__ W3, const float* __restrict__ b3,
                      float* __restrict__ out) {
    __shared__ float sW1[64 * 32], sW2[32 * 16], sb1[32], sb2[16], sW3[16], sb3;
    int tid = threadIdx.x;
    for (int i = tid; i < 64 * 32; i += 256) sW1[i] = W1[i];
    for (int i = tid; i < 32 * 16; i += 256) sW2[i] = W2[i];
    if (tid < 32) sb1[tid] = b1[tid];
    if (tid < 16) { sb2[tid] = b2[tid]; sW3[tid] = W3[tid]; }
    if (tid == 0) sb3 = b3[0];
    __syncthreads();
    int g = tid;
    float inv = 1.f / fmaxf((float)g_gcount[g], 1.f);
    float x[64];
    #pragma unroll
    for (int k = 0; k < 64; k++) x[k] = g_hg[g * 64 + k] * inv;
    float y[32];
    #pragma unroll
    for (int j = 0; j < 32; j++) {
        float a = sb1[j];
        #pragma unroll
        for (int k = 0; k < 64; k++) a += x[k] * sW1[k * 32 + j];
        y[j] = fmaxf(a, 0.f);
    }
    float z[16];
    #pragma unroll
    for (int j = 0; j < 16; j++) {
        float a = sb2[j];
        #pragma unroll
        for (int k = 0; k < 32; k++) a += y[k] * sW2[k * 16 + j];
        z[j] = fmaxf(a, 0.f);
    }
    float o = sb3;
    #pragma unroll
    for (int k = 0; k < 16; k++) o += z[k] * sW3[k];
    out[g] = o;
}

// ---------------- launch ----------------
extern "C" void kernel_launch(void* const* d_in, const int* in_sizes, int n_in,
                              void* d_out, int out_size) {
    const int*   h         = (const int*)d_in[0];
    const int*   e         = (const int*)d_in[1];
    const int*   src       = (const int*)d_in[2];
    const int*   dst       = (const int*)d_in[3];
    const int*   graph_ids = (const int*)d_in[4];
    const float* node_emb  = (const float*)d_in[5];
    const float* edge_emb  = (const float*)d_in[6];
    const float* bn_h_g    = (const float*)d_in[7];
    const float* bn_h_b    = (const float*)d_in[8];
    const float* bn_e_g    = (const float*)d_in[9];
    const float* bn_e_b    = (const float*)d_in[10];
    const float* W1        = (const float*)d_in[11];
    const float* b1        = (const float*)d_in[12];
    const float* W2        = (const float*)d_in[13];
    const float* b2        = (const float*)d_in[14];
    const float* W3        = (const float*)d_in[15];
    const float* b3        = (const float*)d_in[16];
    float* out = (float*)d_out;

    const int NODE_WARP_BLOCKS = (N_NODES_C + 7) / 8;
    const int NL_BLOCKS = (N_NODES_C * 32 + 255) / 256;

    k_init<<<(N_NODES_C + 255) / 256, 256>>>();
    k_deg<<<(N_EDGES_C + 255) / 256, 256>>>(dst, graph_ids);
    k_nodeinit<<<NODE_WARP_BLOCKS, 256>>>(h, node_emb);
    k_scanA<<<N_TILES, SCAN_TILE>>>();
    k_scanB<<<1, 64>>>();
    k_scanC<<<N_TILES, SCAN_TILE>>>();
    k_permute<<<(N_EDGES_C + 255) / 256, 256>>>(e, src, dst, h);

    k_fused<0><<<NODE_WARP_BLOCKS, 256>>>(edge_emb, node_emb);
    k_finalize<<<1, 64>>>(bn_h_g, bn_h_b, bn_e_g, bn_e_b, 0);
    k_Bh<<<NL_BLOCKS, 256>>>();
    k_fused<1><<<NODE_WARP_BLOCKS, 256>>>(edge_emb, node_emb);
    k_finalize<<<1, 64>>>(bn_h_g, bn_h_b, bn_e_g, bn_e_b, 1);
    k_Bh<<<NL_BLOCKS, 256>>>();
    k_fused<2><<<NODE_WARP_BLOCKS, 256>>>(edge_emb, node_emb);
    k_finalize<<<1, 64>>>(bn_h_g, bn_h_b, bn_e_g, bn_e_b, 2);
    k_Bh<<<NL_BLOCKS, 256>>>();
    k_fused<3><<<NODE_WARP_BLOCKS, 256>>>(edge_emb, node_emb);
    k_finalize<<<1, 64>>>(bn_h_g, bn_h_b, bn_e_g, bn_e_b, 3);
    k_BhPool<<<NL_BLOCKS, 256>>>(graph_ids);

    k_mlp<<<1, 256>>>(W1, b1, W2, b2, W3, b3, out);
    (void)in_sizes; (void)n_in; (void)out_size;
}

// round 9
// speedup vs baseline: 1.0912x; 1.0115x over previous
#include <cuda_runtime.h>
#include <cuda_fp16.h>

#define N_NODES_C 50000
#define N_EDGES_C 800000
#define HID_C 64
#define N_GRAPHS_C 256
#define BN_EPS_C 1e-5f
#define GATE_EPS_C 1e-6f
#define SCAN_TILE 1024
#define N_TILES ((N_NODES_C + SCAN_TILE - 1) / SCAN_TILE)

// ---------------- persistent device scratch ----------------
// interleaved node features: per node, 32 float4 = (cur[2l], cur[2l+1], prev[2l], prev[2l+1])
__device__ float4 g_hfi[(size_t)N_NODES_C * 32];
__device__ __half2 g_efh[(size_t)N_EDGES_C * 32];  // edge features fp16 (dst-sorted)
__device__ float g_hpre[N_NODES_C * HID_C];        // pre-BN h_new
__device__ float g_norm[N_NODES_C];
__device__ int   g_deg[N_NODES_C];
__device__ int   g_cursor[N_NODES_C];
__device__ int   g_rowptr[N_NODES_C + 1];
__device__ int   g_srcs[N_EDGES_C];                // packed: src(16) | etype(2)<<16 | hidx(7)<<18
__device__ int   g_bsum[N_TILES];
__device__ int   g_boff[N_TILES];
__device__ float g_stats[4 * HID_C];               // [se, se2, sh, sh2]
__device__ float g_scale_h[HID_C], g_shift_h[HID_C];
__device__ float g_scale_e[HID_C], g_shift_e[HID_C];
__device__ float g_hg[N_GRAPHS_C * HID_C];
__device__ int   g_gcount[N_GRAPHS_C];

// ---- streaming (evict-first) access helpers for the big ef array ----
__device__ __forceinline__ unsigned long long mk_policy() {
    unsigned long long p;
    asm volatile("createpolicy.fractional.L2::evict_first.b64 %0, 1.0;" : "=l"(p));
    return p;
}
__device__ __forceinline__ unsigned ld_stream_b32(const void* ptr, unsigned long long pol) {
    unsigned v;
    asm volatile("ld.global.L2::cache_hint.b32 %0, [%1], %2;"
                 : "=r"(v) : "l"(ptr), "l"(pol));
    return v;
}
__device__ __forceinline__ void st_stream_b32(void* ptr, unsigned v, unsigned long long pol) {
    asm volatile("st.global.L2::cache_hint.b32 [%0], %1, %2;"
                 :: "l"(ptr), "r"(v), "l"(pol));
}

// sigmoid via single-MUFU hardware tanh: sigma(x) = 0.5*tanh(x/2) + 0.5
__device__ __forceinline__ float fast_sigmoid(float x) {
    float t;
    asm("tanh.approx.f32 %0, %1;" : "=f"(t) : "f"(x * 0.5f));
    return fmaf(t, 0.5f, 0.5f);
}

// ---------------- prep kernels ----------------

__global__ void k_init() {
    int i = blockIdx.x * blockDim.x + threadIdx.x;
    if (i < N_NODES_C) { g_deg[i] = 0; g_cursor[i] = 0; }
    if (i < N_GRAPHS_C * HID_C) g_hg[i] = 0.f;
    if (i < N_GRAPHS_C) g_gcount[i] = 0;
    if (i < 4 * HID_C) g_stats[i] = 0.f;
}

__global__ void k_deg(const int* __restrict__ dst, const int* __restrict__ graph_ids) {
    int i = blockIdx.x * blockDim.x + threadIdx.x;
    if (i < N_EDGES_C) atomicAdd(&g_deg[dst[i]], 1);
    if (i < N_NODES_C) atomicAdd(&g_gcount[graph_ids[i]], 1);
}

__global__ void k_nodeinit(const int* __restrict__ h, const float* __restrict__ node_emb) {
    int tid = threadIdx.x;
    int warp = tid >> 5, lane = tid & 31;
    int n = blockIdx.x * 8 + warp;
    if (n >= N_NODES_C) return;
    if (lane == 0) g_norm[n] = rsqrtf(fmaxf((float)g_deg[n], 1.f));
    int hi = h[n];
    float2 v = *(const float2*)(node_emb + hi * HID_C + 2 * lane);
    g_hfi[(size_t)n * 32 + lane] = make_float4(v.x, v.y, v.x, v.y);
}

// ---- 3-phase scan: deg -> rowptr ----
__global__ void k_scanA() {
    __shared__ int s[32];
    int b = blockIdx.x, tid = threadIdx.x;
    int i = b * SCAN_TILE + tid;
    int v = (i < N_NODES_C) ? g_deg[i] : 0;
    #pragma unroll
    for (int off = 16; off > 0; off >>= 1) v += __shfl_down_sync(0xFFFFFFFFu, v, off);
    if ((tid & 31) == 0) s[tid >> 5] = v;
    __syncthreads();
    if (tid < 32) {
        int w = s[tid];
        #pragma unroll
        for (int off = 16; off > 0; off >>= 1) w += __shfl_down_sync(0xFFFFFFFFu, w, off);
        if (tid == 0) g_bsum[b] = w;
    }
}

__global__ void k_scanB() {
    int tid = threadIdx.x;
    int v = (tid < N_TILES) ? g_bsum[tid] : 0;
    int x = v;
    #pragma unroll
    for (int off = 1; off < 64; off <<= 1) {
        int t = __shfl_up_sync(0xFFFFFFFFu, x, off);
        if ((tid & 31) >= off) x += t;
    }
    __shared__ int s_half;
    if (tid == 31) s_half = x;
    __syncthreads();
    if (tid >= 32) x += s_half;
    if (tid < N_TILES) g_boff[tid] = x - v;
}

__global__ void k_scanC() {
    __shared__ int s_warp[32];
    int b = blockIdx.x, tid = threadIdx.x;
    int lane = tid & 31, warp = tid >> 5;
    int i = b * SCAN_TILE + tid;
    int v = (i < N_NODES_C) ? g_deg[i] : 0;
    int x = v;
    #pragma unroll
    for (int off = 1; off < 32; off <<= 1) {
        int t = __shfl_up_sync(0xFFFFFFFFu, x, off);
        if (lane >= off) x += t;
    }
    if (lane == 31) s_warp[warp] = x;
    __syncthreads();
    if (warp == 0) {
        int w = s_warp[lane];
        #pragma unroll
        for (int off = 1; off < 32; off <<= 1) {
            int t = __shfl_up_sync(0xFFFFFFFFu, w, off);
            if (lane >= off) w += t;
        }
        s_warp[lane] = w;
    }
    __syncthreads();
    int incl = x + (warp > 0 ? s_warp[warp - 1] : 0) + g_boff[b];
    if (i < N_NODES_C) g_rowptr[i + 1] = incl;
    if (b == 0 && tid == 0) g_rowptr[0] = 0;
}

// counting-sort permute; packs src | etype<<16 | h[src]<<18
__global__ void k_permute(const int* __restrict__ e, const int* __restrict__ src,
                          const int* __restrict__ dst, const int* __restrict__ h) {
    int i = blockIdx.x * blockDim.x + threadIdx.x;
    if (i >= N_EDGES_C) return;
    int d = dst[i];
    int s = src[i];
    int pos = g_rowptr[d] + atomicAdd(&g_cursor[d], 1);
    g_srcs[pos] = s | (e[i] << 16) | (h[s] << 18);
}

// ---------------- fused layer pass ----------------
// 1 warp/node, 4-wide batches, software-pipelined: next batch's srcs + ef
// stream loads are issued before the current batch's compute.
template<int L>
__global__ void __launch_bounds__(256) k_fused(const float* __restrict__ edge_emb,
                                               const float* __restrict__ node_emb) {
    __shared__ float s_emb[4 * HID_C];
    __shared__ float s_acc[256];
    int tid = threadIdx.x;
    if (L <= 1) s_emb[tid] = edge_emb[tid];
    s_acc[tid] = 0.f;
    __syncthreads();
    int warp = tid >> 5, lane = tid & 31;
    int n = blockIdx.x * 8 + warp;
    if (n < N_NODES_C) {
        unsigned long long pol = mk_policy();
        float4 f4 = g_hfi[(size_t)n * 32 + lane];
        float hdcx = f4.x, hdcy = f4.y, hdpx = f4.z, hdpy = f4.w;
        float sce_x = 0.f, sce_y = 0.f, she_x = 0.f, she_y = 0.f;
        if (L >= 1) {
            sce_x = g_scale_e[2 * lane]; sce_y = g_scale_e[2 * lane + 1];
            she_x = g_shift_e[2 * lane]; she_y = g_shift_e[2 * lane + 1];
        }
        float nn = g_norm[n];
        float mx = 0.f, my = 0.f, dx = 0.f, dy = 0.f;
        float sex = 0.f, sey = 0.f, se2x = 0.f, se2y = 0.f;
        int beg = g_rowptr[n], end = g_rowptr[n + 1];
        int nb = (end - beg) >> 2;              // full 4-edge batches

        auto fetch_nf = [&](int sp, float2& nc, float2& np) {
            int s = sp & 0xFFFF;
            if (L == 0) {
                int hidx = (sp >> 18) & 0x7F;
                nc = __ldg((const float2*)(node_emb + hidx * HID_C + 2 * lane));
                np = make_float2(0.f, 0.f);
            } else if (L == 1) {
                nc = *(const float2*)&g_hfi[(size_t)s * 32 + lane];   // cur half (8B)
                int hidx = (sp >> 18) & 0x7F;
                np = __ldg((const float2*)(node_emb + hidx * HID_C + 2 * lane));
            } else {
                float4 v = g_hfi[(size_t)s * 32 + lane];
                nc = make_float2(v.x, v.y);
                np = make_float2(v.z, v.w);
            }
        };

        auto compute = [&](int k, float2 nc, float2 np, float ns, float rawx, float rawy) {
            float efx, efy;
            if (L == 0) {
                efx = rawx; efy = rawy;
            } else {
                float epx = np.x + hdpx + rawx;
                float epy = np.y + hdpy + rawy;
                efx = rawx + fmaxf(epx * sce_x + she_x, 0.f);
                efy = rawy + fmaxf(epy * sce_y + she_y, 0.f);
                if (L < 3) {
                    __half2 hv = __floats2half2_rn(efx, efy);
                    st_stream_b32(&g_efh[(size_t)k * 32 + lane], *(unsigned*)&hv, pol);
                }
            }
            float ex = nc.x + hdcx + efx;
            float ey = nc.y + hdcy + efy;
            float sgx = fast_sigmoid(ex);
            float sgy = fast_sigmoid(ey);
            mx += sgx * nc.x * ns; my += sgy * nc.y * ns;
            dx += sgx; dy += sgy;
            if (L < 3) { sex += ex; sey += ey; se2x += ex * ex; se2y += ey * ey; }
        };

        // ---- software-pipelined main loop ----
        int spA[4], spB[4];
        unsigned efA[4], efB[4];
        if (nb > 0) {
            #pragma unroll
            for (int j = 0; j < 4; j++) spA[j] = g_srcs[beg + j];
            if (L >= 2) {
                #pragma unroll
                for (int j = 0; j < 4; j++)
                    efA[j] = ld_stream_b32(&g_efh[(size_t)(beg + j) * 32 + lane], pol);
            }
        }
        for (int b = 0; b < nb; b++) {
            int kk = beg + b * 4;
            // prefetch next batch's sequential streams
            if (b + 1 < nb) {
                #pragma unroll
                for (int j = 0; j < 4; j++) spB[j] = g_srcs[kk + 4 + j];
                if (L >= 2) {
                    #pragma unroll
                    for (int j = 0; j < 4; j++)
                        efB[j] = ld_stream_b32(&g_efh[(size_t)(kk + 4 + j) * 32 + lane], pol);
                }
            }
            // gather current batch's node data
            float2 nc[4], np[4];
            #pragma unroll
            for (int j = 0; j < 4; j++) fetch_nf(spA[j], nc[j], np[j]);
            float ns[4];
            #pragma unroll
            for (int j = 0; j < 4; j++) ns[j] = g_norm[spA[j] & 0xFFFF];
            float rawx[4], rawy[4];
            #pragma unroll
            for (int j = 0; j < 4; j++) {
                if (L <= 1) {
                    int et = (spA[j] >> 16) & 3;
                    rawx[j] = s_emb[et * HID_C + 2 * lane];
                    rawy[j] = s_emb[et * HID_C + 2 * lane + 1];
                } else {
                    float2 r = __half22float2(*(__half2*)&efA[j]);
                    rawx[j] = r.x; rawy[j] = r.y;
                }
            }
            #pragma unroll
            for (int j = 0; j < 4; j++) compute(kk + j, nc[j], np[j], ns[j], rawx[j], rawy[j]);
            #pragma unroll
            for (int j = 0; j < 4; j++) { spA[j] = spB[j]; efA[j] = efB[j]; }
        }
        // tail
        for (int k = beg + nb * 4; k < end; k++) {
            int sp = g_srcs[k];
            float2 nc, np;
            fetch_nf(sp, nc, np);
            float ns = g_norm[sp & 0xFFFF];
            float rawx, rawy;
            if (L <= 1) {
                int et = (sp >> 16) & 3;
                rawx = s_emb[et * HID_C + 2 * lane];
                rawy = s_emb[et * HID_C + 2 * lane + 1];
            } else {
                unsigned u = ld_stream_b32(&g_efh[(size_t)k * 32 + lane], pol);
                float2 r = __half22float2(*(__half2*)&u);
                rawx = r.x; rawy = r.y;
            }
            compute(k, nc, np, ns, rawx, rawy);
        }

        float hpx = (hdcx * nn + mx / (dx + GATE_EPS_C)) * nn;
        float hpy = (hdcy * nn + my / (dy + GATE_EPS_C)) * nn;
        *(float2*)(&g_hpre[n * HID_C + 2 * lane]) = make_float2(hpx, hpy);
        if (L < 3) {
            atomicAdd(&s_acc[2 * lane], sex);
            atomicAdd(&s_acc[2 * lane + 1], sey);
            atomicAdd(&s_acc[64 + 2 * lane], se2x);
            atomicAdd(&s_acc[64 + 2 * lane + 1], se2y);
        }
        atomicAdd(&s_acc[128 + 2 * lane], hpx);
        atomicAdd(&s_acc[128 + 2 * lane + 1], hpy);
        atomicAdd(&s_acc[192 + 2 * lane], hpx * hpx);
        atomicAdd(&s_acc[192 + 2 * lane + 1], hpy * hpy);
    }
    __syncthreads();
    atomicAdd(&g_stats[tid], s_acc[tid]);
}

// BN scale/shift for layer l; reset stats
__global__ void k_finalize(const float* __restrict__ bhg, const float* __restrict__ bhb,
                           const float* __restrict__ beg_, const float* __restrict__ beb, int l) {
    int f = threadIdx.x;
    float se = g_stats[f], se2 = g_stats[64 + f];
    float sh = g_stats[128 + f], sh2 = g_stats[192 + f];
    float mue = se / (float)N_EDGES_C;
    float vare = se2 / (float)N_EDGES_C - mue * mue;
    float sce = beg_[l * HID_C + f] * rsqrtf(vare + BN_EPS_C);
    g_scale_e[f] = sce;
    g_shift_e[f] = beb[l * HID_C + f] - mue * sce;
    float muh = sh / (float)N_NODES_C;
    float varh = sh2 / (float)N_NODES_C - muh * muh;
    float sch = bhg[l * HID_C + f] * rsqrtf(varh + BN_EPS_C);
    g_scale_h[f] = sch;
    g_shift_h[f] = bhb[l * HID_C + f] - muh * sch;
    g_stats[f] = 0.f; g_stats[64 + f] = 0.f; g_stats[128 + f] = 0.f; g_stats[192 + f] = 0.f;
}

// node update on interleaved array: (cur, prev) -> (cur + relu(BN(hpre)), cur)
__global__ void k_Bh() {
    int i = blockIdx.x * blockDim.x + threadIdx.x;
    if (i >= N_NODES_C * 32) return;
    int lane = i & 31;
    float4 f4 = g_hfi[i];
    float2 hp = *(const float2*)(&g_hpre[i * 2]);
    float vx = fmaxf(hp.x * g_scale_h[2 * lane] + g_shift_h[2 * lane], 0.f);
    float vy = fmaxf(hp.y * g_scale_h[2 * lane + 1] + g_shift_h[2 * lane + 1], 0.f);
    g_hfi[i] = make_float4(f4.x + vx, f4.y + vy, f4.x, f4.y);
}

// final node update fused with per-graph sum pooling
__global__ void k_BhPool(const int* __restrict__ graph_ids) {
    int i = blockIdx.x * blockDim.x + threadIdx.x;
    if (i >= N_NODES_C * 32) return;
    int lane = i & 31;
    int n = i >> 5;
    float4 f4 = g_hfi[i];
    float2 hp = *(const float2*)(&g_hpre[i * 2]);
    float vx = f4.x + fmaxf(hp.x * g_scale_h[2 * lane] + g_shift_h[2 * lane], 0.f);
    float vy = f4.y + fmaxf(hp.y * g_scale_h[2 * lane + 1] + g_shift_h[2 * lane + 1], 0.f);
    int g = graph_ids[n];
    atomicAdd(&g_hg[(g << 6) + 2 * lane], vx);
    atomicAdd(&g_hg[(g << 6) + 2 * lane + 1], vy);
}

// final 3-layer MLP, one thread per graph
__global__ void k_mlp(const float* __restrict__ W1, const float* __restrict__ b1,
                      const float* __restrict__ W2, const float* __restrict__ b2,
                      const float* __restrict__ W3, const float* __restrict__ b3,
                      float* __restrict__ out) {
    __shared__ float sW1[64 * 32], sW2[32 * 16], sb1[32], sb2[16], sW3[16], sb3;
    int tid = threadIdx.x;
    for (int i = tid; i < 64 * 32; i += 256) sW1[i] = W1[i];
    for (int i = tid; i < 32 * 16; i += 256) sW2[i] = W2[i];
    if (tid < 32) sb1[tid] = b1[tid];
    if (tid < 16) { sb2[tid] = b2[tid]; sW3[tid] = W3[tid]; }
    if (tid == 0) sb3 = b3[0];
    __syncthreads();
    int g = tid;
    float inv = 1.f / fmaxf((float)g_gcount[g], 1.f);
    float x[64];
    #pragma unroll
    for (int k = 0; k < 64; k++) x[k] = g_hg[g * 64 + k] * inv;
    float y[32];
    #pragma unroll
    for (int j = 0; j < 32; j++) {
        float a = sb1[j];
        #pragma unroll
        for (int k = 0; k < 64; k++) a += x[k] * sW1[k * 32 + j];
        y[j] = fmaxf(a, 0.f);
    }
    float z[16];
    #pragma unroll
    for (int j = 0; j < 16; j++) {
        float a = sb2[j];
        #pragma unroll
        for (int k = 0; k < 32; k++) a += y[k] * sW2[k * 16 + j];
        z[j] = fmaxf(a, 0.f);
    }
    float o = sb3;
    #pragma unroll
    for (int k = 0; k < 16; k++) o += z[k] * sW3[k];
    out[g] = o;
}

// ---------------- launch ----------------
extern "C" void kernel_launch(void* const* d_in, const int* in_sizes, int n_in,
                              void* d_out, int out_size) {
    const int*   h         = (const int*)d_in[0];
    const int*   e         = (const int*)d_in[1];
    const int*   src       = (const int*)d_in[2];
    const int*   dst       = (const int*)d_in[3];
    const int*   graph_ids = (const int*)d_in[4];
    const float* node_emb  = (const float*)d_in[5];
    const float* edge_emb  = (const float*)d_in[6];
    const float* bn_h_g    = (const float*)d_in[7];
    const float* bn_h_b    = (const float*)d_in[8];
    const float* bn_e_g    = (const float*)d_in[9];
    const float* bn_e_b    = (const float*)d_in[10];
    const float* W1        = (const float*)d_in[11];
    const float* b1        = (const float*)d_in[12];
    const float* W2        = (const float*)d_in[13];
    const float* b2        = (const float*)d_in[14];
    const float* W3        = (const float*)d_in[15];
    const float* b3        = (const float*)d_in[16];
    float* out = (float*)d_out;

    const int NODE_WARP_BLOCKS = (N_NODES_C + 7) / 8;
    const int NL_BLOCKS = (N_NODES_C * 32 + 255) / 256;

    k_init<<<(N_NODES_C + 255) / 256, 256>>>();
    k_deg<<<(N_EDGES_C + 255) / 256, 256>>>(dst, graph_ids);
    k_nodeinit<<<NODE_WARP_BLOCKS, 256>>>(h, node_emb);
    k_scanA<<<N_TILES, SCAN_TILE>>>();
    k_scanB<<<1, 64>>>();
    k_scanC<<<N_TILES, SCAN_TILE>>>();
    k_permute<<<(N_EDGES_C + 255) / 256, 256>>>(e, src, dst, h);

    k_fused<0><<<NODE_WARP_BLOCKS, 256>>>(edge_emb, node_emb);
    k_finalize<<<1, 64>>>(bn_h_g, bn_h_b, bn_e_g, bn_e_b, 0);
    k_Bh<<<NL_BLOCKS, 256>>>();
    k_fused<1><<<NODE_WARP_BLOCKS, 256>>>(edge_emb, node_emb);
    k_finalize<<<1, 64>>>(bn_h_g, bn_h_b, bn_e_g, bn_e_b, 1);
    k_Bh<<<NL_BLOCKS, 256>>>();
    k_fused<2><<<NODE_WARP_BLOCKS, 256>>>(edge_emb, node_emb);
    k_finalize<<<1, 64>>>(bn_h_g, bn_h_b, bn_e_g, bn_e_b, 2);
    k_Bh<<<NL_BLOCKS, 256>>>();
    k_fused<3><<<NODE_WARP_BLOCKS, 256>>>(edge_emb, node_emb);
    k_finalize<<<1, 64>>>(bn_h_g, bn_h_b, bn_e_g, bn_e_b, 3);
    k_BhPool<<<NL_BLOCKS, 256>>>(graph_ids);

    k_mlp<<<1, 256>>>(W1, b1, W2, b2, W3, b3, out);
    (void)in_sizes; (void)n_in; (void)out_size;
}